// round 1
// baseline (speedup 1.0000x reference)
#include <cuda_runtime.h>
#include <math.h>

#define NN 65536
#define EE 1048576
#define NEG 0.2f
#define EPSV 1e-16f

// ---------------- scratch (device globals: allocation-free) ----------------
__device__ int   g_is64;
__device__ int   g_src[EE];
__device__ int   g_dst[EE];
__device__ int   g_deg[NN];
__device__ int   g_off[NN + 1];
__device__ int   g_cur[NN];
__device__ int   g_csr[EE];          // src node id per CSR slot (grouped by dst)
__device__ float g_h1[NN * 128];
__device__ float g_as1[NN * 4];
__device__ float g_ad1[NN * 4];
__device__ float g_out1[NN * 128];
__device__ float g_h2[NN * 64];
__device__ float g_as2[NN];
__device__ float g_ad2[NN];

__device__ __forceinline__ float lrelu(float a) { return a > 0.f ? a : NEG * a; }
__device__ __forceinline__ float sigm(float x) { return 1.f / (1.f + __expf(-x)); }

// ---------------- preprocessing ----------------
__global__ void k_zero_detect(const unsigned int* __restrict__ ei) {
    int i = blockIdx.x * blockDim.x + threadIdx.x;
    for (int j = i; j < NN; j += gridDim.x * blockDim.x) g_deg[j] = 0;
    if (blockIdx.x == 0 && threadIdx.x == 0) {
        // int64 iff the high 32-bit word of the first 128 entries is always 0
        int is64 = 1;
        for (int k = 0; k < 128; k++)
            if (ei[2 * k + 1] != 0u) { is64 = 0; break; }
        g_is64 = is64;
    }
}

__global__ void k_convert(const void* __restrict__ ei) {
    int e = blockIdx.x * blockDim.x + threadIdx.x;
    if (e >= EE) return;
    int s, d;
    if (g_is64) {
        const long long* p = (const long long*)ei;
        s = (int)p[e];
        d = (int)p[EE + e];
    } else {
        const int* p = (const int*)ei;
        s = p[e];
        d = p[EE + e];
    }
    g_src[e] = s;
    g_dst[e] = d;
    atomicAdd(&g_deg[d], 1);
}

__global__ void k_scan() {
    __shared__ int part[1024];
    int tid = threadIdx.x;
    const int per = NN / 1024;  // 64
    int base = tid * per;
    int s = 0;
    for (int i = 0; i < per; i++) s += g_deg[base + i];
    part[tid] = s;
    __syncthreads();
    for (int off = 1; off < 1024; off <<= 1) {
        int v = (tid >= off) ? part[tid - off] : 0;
        __syncthreads();
        part[tid] += v;
        __syncthreads();
    }
    int run = (tid == 0) ? 0 : part[tid - 1];
    for (int i = 0; i < per; i++) {
        g_off[base + i] = run;
        g_cur[base + i] = run;
        run += g_deg[base + i];
    }
    if (tid == 1023) g_off[NN] = part[1023];
}

__global__ void k_csr() {
    int e = blockIdx.x * blockDim.x + threadIdx.x;
    if (e >= EE) return;
    int pos = atomicAdd(&g_cur[g_dst[e]], 1);
    g_csr[pos] = g_src[e];
}

// ---------------- SGEMM: H[M,NC] = A[M,128] * W[128,NC] ----------------
template <int NC>
__global__ __launch_bounds__(256) void k_gemm(const float* __restrict__ A,
                                              const float* __restrict__ W,
                                              float* __restrict__ H) {
    const int CG = NC / 4;        // col groups (4 cols each)
    const int TR = (256 / CG) * 4;  // rows per block tile
    __shared__ __align__(16) float xs[TR][33];
    __shared__ __align__(16) float ws[32][NC];
    int t = threadIdx.x;
    int tx = t % CG;
    int ty = t / CG;
    int row0 = blockIdx.x * TR;

    float4 acc[4];
    acc[0] = make_float4(0.f, 0.f, 0.f, 0.f);
    acc[1] = acc[0]; acc[2] = acc[0]; acc[3] = acc[0];

    for (int kc = 0; kc < 4; kc++) {
        for (int idx = t; idx < TR * 32; idx += 256) {
            int r = idx >> 5, k = idx & 31;
            xs[r][k] = A[(row0 + r) * 128 + kc * 32 + k];
        }
        for (int idx = t; idx < 32 * NC; idx += 256) {
            int kk = idx / NC, c = idx % NC;
            ws[kk][c] = W[(kc * 32 + kk) * NC + c];
        }
        __syncthreads();
#pragma unroll
        for (int k = 0; k < 32; k++) {
            float4 wv = *(const float4*)&ws[k][tx * 4];
#pragma unroll
            for (int i = 0; i < 4; i++) {
                float xv = xs[ty * 4 + i][k];
                acc[i].x += xv * wv.x;
                acc[i].y += xv * wv.y;
                acc[i].z += xv * wv.z;
                acc[i].w += xv * wv.w;
            }
        }
        __syncthreads();
    }
#pragma unroll
    for (int i = 0; i < 4; i++)
        *(float4*)&H[(row0 + ty * 4 + i) * NC + tx * 4] = acc[i];
}

// ---------------- attention dot products ----------------
__global__ void k_att1(const float* __restrict__ h, const float* __restrict__ ats,
                       const float* __restrict__ atd) {
    int w = (blockIdx.x * blockDim.x + threadIdx.x) >> 5;
    int lane = threadIdx.x & 31;
    if (w >= NN) return;
    const float* hp = h + w * 128;
    float sv[4], dv[4];
#pragma unroll
    for (int k = 0; k < 4; k++) {
        float hv = hp[k * 32 + lane];
        sv[k] = hv * ats[k * 32 + lane];
        dv[k] = hv * atd[k * 32 + lane];
    }
#pragma unroll
    for (int off = 16; off > 0; off >>= 1) {
#pragma unroll
        for (int k = 0; k < 4; k++) {
            sv[k] += __shfl_xor_sync(0xffffffffu, sv[k], off);
            dv[k] += __shfl_xor_sync(0xffffffffu, dv[k], off);
        }
    }
    if (lane == 0) {
#pragma unroll
        for (int k = 0; k < 4; k++) {
            g_as1[w * 4 + k] = sv[k];
            g_ad1[w * 4 + k] = dv[k];
        }
    }
}

__global__ void k_att2(const float* __restrict__ h, const float* __restrict__ ats,
                       const float* __restrict__ atd) {
    int w = (blockIdx.x * blockDim.x + threadIdx.x) >> 5;
    int lane = threadIdx.x & 31;
    if (w >= NN) return;
    const float* hp = h + w * 64;
    float sv = hp[lane] * ats[lane] + hp[32 + lane] * ats[32 + lane];
    float dv = hp[lane] * atd[lane] + hp[32 + lane] * atd[32 + lane];
#pragma unroll
    for (int off = 16; off > 0; off >>= 1) {
        sv += __shfl_xor_sync(0xffffffffu, sv, off);
        dv += __shfl_xor_sync(0xffffffffu, dv, off);
    }
    if (lane == 0) {
        g_as2[w] = sv;
        g_ad2[w] = dv;
    }
}

// ---------------- layer-1 aggregation: warp per dst node ----------------
__global__ void k_agg1(const float* __restrict__ h, const float* __restrict__ b,
                       float* __restrict__ out) {
    int n = (blockIdx.x * blockDim.x + threadIdx.x) >> 5;
    int lane = threadIdx.x & 31;
    if (n >= NN) return;
    int beg = g_off[n], end = g_off[n + 1];
    float4 ad = *(const float4*)&g_ad1[n * 4];

    float m0 = -1e30f, m1 = -1e30f, m2 = -1e30f, m3 = -1e30f;
    for (int e = beg + lane; e < end; e += 32) {
        int s = g_csr[e];
        float4 as = *(const float4*)&g_as1[s * 4];
        m0 = fmaxf(m0, lrelu(as.x + ad.x));
        m1 = fmaxf(m1, lrelu(as.y + ad.y));
        m2 = fmaxf(m2, lrelu(as.z + ad.z));
        m3 = fmaxf(m3, lrelu(as.w + ad.w));
    }
#pragma unroll
    for (int off = 16; off > 0; off >>= 1) {
        m0 = fmaxf(m0, __shfl_xor_sync(0xffffffffu, m0, off));
        m1 = fmaxf(m1, __shfl_xor_sync(0xffffffffu, m1, off));
        m2 = fmaxf(m2, __shfl_xor_sync(0xffffffffu, m2, off));
        m3 = fmaxf(m3, __shfl_xor_sync(0xffffffffu, m3, off));
    }

    float s0 = 0.f, s1 = 0.f, s2 = 0.f, s3 = 0.f;
    for (int e = beg + lane; e < end; e += 32) {
        int s = g_csr[e];
        float4 as = *(const float4*)&g_as1[s * 4];
        s0 += __expf(lrelu(as.x + ad.x) - m0);
        s1 += __expf(lrelu(as.y + ad.y) - m1);
        s2 += __expf(lrelu(as.z + ad.z) - m2);
        s3 += __expf(lrelu(as.w + ad.w) - m3);
    }
#pragma unroll
    for (int off = 16; off > 0; off >>= 1) {
        s0 += __shfl_xor_sync(0xffffffffu, s0, off);
        s1 += __shfl_xor_sync(0xffffffffu, s1, off);
        s2 += __shfl_xor_sync(0xffffffffu, s2, off);
        s3 += __shfl_xor_sync(0xffffffffu, s3, off);
    }
    float r0 = 1.f / (s0 + EPSV);
    float r1 = 1.f / (s1 + EPSV);
    float r2 = 1.f / (s2 + EPSV);
    float r3 = 1.f / (s3 + EPSV);

    float a0 = 0.f, a1 = 0.f, a2 = 0.f, a3 = 0.f;
    for (int e = beg; e < end; e++) {
        int s = g_csr[e];  // same addr all lanes: broadcast
        float4 as = *(const float4*)&g_as1[s * 4];
        float w0 = __expf(lrelu(as.x + ad.x) - m0) * r0;
        float w1 = __expf(lrelu(as.y + ad.y) - m1) * r1;
        float w2 = __expf(lrelu(as.z + ad.z) - m2) * r2;
        float w3 = __expf(lrelu(as.w + ad.w) - m3) * r3;
        const float* hp = h + s * 128;
        a0 += w0 * hp[lane];
        a1 += w1 * hp[32 + lane];
        a2 += w2 * hp[64 + lane];
        a3 += w3 * hp[96 + lane];
    }
    out[n * 128 + lane]      = sigm(a0 + b[lane]);
    out[n * 128 + 32 + lane] = sigm(a1 + b[32 + lane]);
    out[n * 128 + 64 + lane] = sigm(a2 + b[64 + lane]);
    out[n * 128 + 96 + lane] = sigm(a3 + b[96 + lane]);
}

// ---------------- layer-2 aggregation (heads=1, C=64) ----------------
__global__ void k_agg2(const float* __restrict__ h, const float* __restrict__ b,
                       float* __restrict__ out) {
    int n = (blockIdx.x * blockDim.x + threadIdx.x) >> 5;
    int lane = threadIdx.x & 31;
    if (n >= NN) return;
    int beg = g_off[n], end = g_off[n + 1];
    float ad = g_ad2[n];

    float m = -1e30f;
    for (int e = beg + lane; e < end; e += 32)
        m = fmaxf(m, lrelu(g_as2[g_csr[e]] + ad));
#pragma unroll
    for (int off = 16; off > 0; off >>= 1)
        m = fmaxf(m, __shfl_xor_sync(0xffffffffu, m, off));

    float ssum = 0.f;
    for (int e = beg + lane; e < end; e += 32)
        ssum += __expf(lrelu(g_as2[g_csr[e]] + ad) - m);
#pragma unroll
    for (int off = 16; off > 0; off >>= 1)
        ssum += __shfl_xor_sync(0xffffffffu, ssum, off);
    float r = 1.f / (ssum + EPSV);

    float a0 = 0.f, a1 = 0.f;
    for (int e = beg; e < end; e++) {
        int s = g_csr[e];
        float w = __expf(lrelu(g_as2[s] + ad) - m) * r;
        const float* hp = h + s * 64;
        a0 += w * hp[lane];
        a1 += w * hp[32 + lane];
    }
    out[n * 64 + lane]      = sigm(a0 + b[lane]);
    out[n * 64 + 32 + lane] = sigm(a1 + b[32 + lane]);
}

// ---------------- launch ----------------
extern "C" void kernel_launch(void* const* d_in, const int* in_sizes, int n_in,
                              void* d_out, int out_size) {
    const float* x   = (const float*)d_in[0];
    const void*  ei  = d_in[1];
    const float* W1  = (const float*)d_in[2];
    const float* at_s1 = (const float*)d_in[3];
    const float* at_d1 = (const float*)d_in[4];
    const float* b1  = (const float*)d_in[5];
    const float* W2  = (const float*)d_in[6];
    const float* at_s2 = (const float*)d_in[7];
    const float* at_d2 = (const float*)d_in[8];
    const float* b2  = (const float*)d_in[9];
    float* out = (float*)d_out;

    float *h1p, *out1p, *h2p;
    cudaGetSymbolAddress((void**)&h1p, g_h1);
    cudaGetSymbolAddress((void**)&out1p, g_out1);
    cudaGetSymbolAddress((void**)&h2p, g_h2);

    k_zero_detect<<<256, 256>>>((const unsigned int*)ei);
    k_convert<<<EE / 256, 256>>>(ei);
    k_scan<<<1, 1024>>>();
    k_csr<<<EE / 256, 256>>>();

    // layer 1
    k_gemm<128><<<NN / 32, 256>>>(x, W1, h1p);
    k_att1<<<NN / 8, 256>>>(h1p, at_s1, at_d1);
    k_agg1<<<NN / 8, 256>>>(h1p, b1, out1p);

    // layer 2
    k_gemm<64><<<NN / 64, 256>>>(out1p, W2, h2p);
    k_att2<<<NN / 8, 256>>>(h2p, at_s2, at_d2);
    k_agg2<<<NN / 8, 256>>>(h2p, b2, out);
}

// round 3
// speedup vs baseline: 1.0754x; 1.0754x over previous
#include <cuda_runtime.h>
#include <cuda_bf16.h>
#include <stdint.h>
#include <math.h>

#define NN 65536
#define EE 1048576
#define NEG 0.2f
#define EPSV 1e-16f

// ---------------- scratch (device globals: allocation-free) ----------------
__device__ int   g_is64;
__device__ int   g_src[EE];
__device__ int   g_dst[EE];
__device__ int   g_deg[NN];
__device__ int   g_off[NN + 1];
__device__ int   g_cur[NN];
__device__ int   g_csr[EE];
__device__ float g_h1[NN * 128];
__device__ float g_as1[NN * 4];
__device__ float g_ad1[NN * 4];
__device__ float g_out1[NN * 128];
__device__ float g_h2[NN * 64];
__device__ float g_as2[NN];
__device__ float g_ad2[NN];

__device__ __forceinline__ float lrelu(float a) { return a > 0.f ? a : NEG * a; }
__device__ __forceinline__ float sigm(float x) { return 1.f / (1.f + __expf(-x)); }
__device__ __forceinline__ uint32_t pack_bf2(__nv_bfloat16 a, __nv_bfloat16 b) {
    return ((uint32_t)__bfloat16_as_ushort(b) << 16) | (uint32_t)__bfloat16_as_ushort(a);
}

__device__ __forceinline__ void mma16816(float* c, const uint32_t* a, const uint32_t* b) {
    asm volatile(
        "mma.sync.aligned.m16n8k16.row.col.f32.bf16.bf16.f32 "
        "{%0,%1,%2,%3}, {%4,%5,%6,%7}, {%8,%9}, {%0,%1,%2,%3};"
        : "+f"(c[0]), "+f"(c[1]), "+f"(c[2]), "+f"(c[3])
        : "r"(a[0]), "r"(a[1]), "r"(a[2]), "r"(a[3]), "r"(b[0]), "r"(b[1]));
}

// ---------------- preprocessing ----------------
__global__ void k_zero_detect(const unsigned int* __restrict__ ei) {
    int i = blockIdx.x * blockDim.x + threadIdx.x;
    for (int j = i; j < NN; j += gridDim.x * blockDim.x) g_deg[j] = 0;
    if (blockIdx.x == 0 && threadIdx.x == 0) {
        int is64 = 1;
        for (int k = 0; k < 128; k++)
            if (ei[2 * k + 1] != 0u) { is64 = 0; break; }
        g_is64 = is64;
    }
}

__global__ void k_convert(const void* __restrict__ ei) {
    int e = blockIdx.x * blockDim.x + threadIdx.x;
    if (e >= EE) return;
    int s, d;
    if (g_is64) {
        const long long* p = (const long long*)ei;
        s = (int)p[e];
        d = (int)p[EE + e];
    } else {
        const int* p = (const int*)ei;
        s = p[e];
        d = p[EE + e];
    }
    g_src[e] = s;
    g_dst[e] = d;
    atomicAdd(&g_deg[d], 1);
}

__global__ void k_scan() {
    __shared__ int part[1024];
    int tid = threadIdx.x;
    const int per = NN / 1024;
    int base = tid * per;
    int s = 0;
    for (int i = 0; i < per; i++) s += g_deg[base + i];
    part[tid] = s;
    __syncthreads();
    for (int off = 1; off < 1024; off <<= 1) {
        int v = (tid >= off) ? part[tid - off] : 0;
        __syncthreads();
        part[tid] += v;
        __syncthreads();
    }
    int run = (tid == 0) ? 0 : part[tid - 1];
    for (int i = 0; i < per; i++) {
        g_off[base + i] = run;
        g_cur[base + i] = run;
        run += g_deg[base + i];
    }
    if (tid == 1023) g_off[NN] = part[1023];
}

__global__ void k_csr() {
    int e = blockIdx.x * blockDim.x + threadIdx.x;
    if (e >= EE) return;
    int pos = atomicAdd(&g_cur[g_dst[e]], 1);
    g_csr[pos] = g_src[e];
}

// ---------------- fused HMMA GEMM + attention dots ----------------
// D[128, NB] = A[128,128] * W[128,NB], bf16 hi/lo 3-pass, fp32 accum.
// Epilogue fuses per-row attention dot products.
template <int NB, int HEADS_T, int HC>
__global__ void __launch_bounds__(256, 1) k_mma(
    const float* __restrict__ A, const float* __restrict__ Wsrc,
    const float* __restrict__ ats, const float* __restrict__ atd,
    float* __restrict__ Hout, float* __restrict__ as_out, float* __restrict__ ad_out) {
    constexpr int PITCH = 136;  // bf16 elems/row: 4-bank shift per row -> conflict-free frags
    constexpr int NT = NB / 8;
    extern __shared__ __align__(16) char smem[];
    __nv_bfloat16* Ah = (__nv_bfloat16*)smem;
    __nv_bfloat16* Al = Ah + 128 * PITCH;
    __nv_bfloat16* Bh = Al + 128 * PITCH;
    __nv_bfloat16* Bl = Bh + NB * PITCH;
    float* s_as = (float*)(Bl + NB * PITCH);
    float* s_ad = s_as + NB;

    int t = threadIdx.x, w = t >> 5, lane = t & 31;
    int gid = lane >> 2, tid4 = lane & 3;
    int row0 = blockIdx.x * 128;

    // ---- A tile: 128x128 fp32 -> hi/lo bf16, row-major pitch 136 ----
#pragma unroll
    for (int i = 0; i < 16; i++) {
        int idx = i * 256 + t;
        int r = idx >> 5, c4 = idx & 31;
        float4 v = *(const float4*)&A[(size_t)(row0 + r) * 128 + c4 * 4];
        __nv_bfloat16 hx = __float2bfloat16(v.x), hy = __float2bfloat16(v.y);
        __nv_bfloat16 hz = __float2bfloat16(v.z), hw = __float2bfloat16(v.w);
        __nv_bfloat16 lx = __float2bfloat16(v.x - __bfloat162float(hx));
        __nv_bfloat16 ly = __float2bfloat16(v.y - __bfloat162float(hy));
        __nv_bfloat16 lz = __float2bfloat16(v.z - __bfloat162float(hz));
        __nv_bfloat16 lw = __float2bfloat16(v.w - __bfloat162float(hw));
        int o = r * PITCH + c4 * 4;
        *(uint2*)&Ah[o] = make_uint2(pack_bf2(hx, hy), pack_bf2(hz, hw));
        *(uint2*)&Al[o] = make_uint2(pack_bf2(lx, ly), pack_bf2(lz, lw));
    }
    // ---- B tile transposed: BT[n][k] = W[k][n], hi/lo ----
    for (int idx = t; idx < 128 * (NB / 4); idx += 256) {
        int k = idx / (NB / 4), n4 = idx % (NB / 4);
        float4 wv4 = *(const float4*)&Wsrc[(size_t)k * NB + n4 * 4];
        float wv[4] = {wv4.x, wv4.y, wv4.z, wv4.w};
#pragma unroll
        for (int j = 0; j < 4; j++) {
            int n = n4 * 4 + j;
            __nv_bfloat16 h = __float2bfloat16(wv[j]);
            Bh[n * PITCH + k] = h;
            Bl[n * PITCH + k] = __float2bfloat16(wv[j] - __bfloat162float(h));
        }
    }
    for (int idx = t; idx < NB; idx += 256) {
        s_as[idx] = ats[idx];
        s_ad[idx] = atd[idx];
    }
    __syncthreads();

    // ---- MMA: warp w owns rows [w*16, w*16+16), all NT n-tiles ----
    int wr = w * 16;
    int r1 = wr + gid, r2 = wr + gid + 8;
    float acc[NT][4];
#pragma unroll
    for (int nt = 0; nt < NT; nt++) {
        acc[nt][0] = 0.f; acc[nt][1] = 0.f; acc[nt][2] = 0.f; acc[nt][3] = 0.f;
    }
    const __nv_bfloat16* PA[3] = {Ah, Ah, Al};
    const __nv_bfloat16* PB[3] = {Bh, Bl, Bh};
#pragma unroll
    for (int p = 0; p < 3; p++) {
        const __nv_bfloat16* pa = PA[p];
        const __nv_bfloat16* pb = PB[p];
#pragma unroll
        for (int kt = 0; kt < 8; kt++) {
            int k0 = kt * 16 + tid4 * 2;
            uint32_t a[4];
            a[0] = *(const uint32_t*)&pa[r1 * PITCH + k0];
            a[1] = *(const uint32_t*)&pa[r2 * PITCH + k0];
            a[2] = *(const uint32_t*)&pa[r1 * PITCH + k0 + 8];
            a[3] = *(const uint32_t*)&pa[r2 * PITCH + k0 + 8];
#pragma unroll
            for (int nt = 0; nt < NT; nt++) {
                uint32_t b[2];
                int nr = nt * 8 + gid;
                b[0] = *(const uint32_t*)&pb[nr * PITCH + k0];
                b[1] = *(const uint32_t*)&pb[nr * PITCH + k0 + 8];
                mma16816(acc[nt], a, b);
            }
        }
    }

    // ---- epilogue: H rows + fused attention dots ----
    float accs[2][HEADS_T], accd[2][HEADS_T];
#pragma unroll
    for (int i = 0; i < 2; i++)
#pragma unroll
        for (int h = 0; h < HEADS_T; h++) { accs[i][h] = 0.f; accd[i][h] = 0.f; }

    int gr1 = row0 + r1, gr2 = row0 + r2;
#pragma unroll
    for (int nt = 0; nt < NT; nt++) {
        constexpr int dummy = 0; (void)dummy;
        const int hidx = (nt * 8) / HC;  // compile-time per nt (8 | HC)
        int c0 = nt * 8 + tid4 * 2;
        float as0 = s_as[c0], as1 = s_as[c0 + 1];
        float ad0 = s_ad[c0], ad1 = s_ad[c0 + 1];
        accs[0][hidx] += acc[nt][0] * as0 + acc[nt][1] * as1;
        accd[0][hidx] += acc[nt][0] * ad0 + acc[nt][1] * ad1;
        accs[1][hidx] += acc[nt][2] * as0 + acc[nt][3] * as1;
        accd[1][hidx] += acc[nt][2] * ad0 + acc[nt][3] * ad1;
        *(float2*)&Hout[(size_t)gr1 * NB + c0] = make_float2(acc[nt][0], acc[nt][1]);
        *(float2*)&Hout[(size_t)gr2 * NB + c0] = make_float2(acc[nt][2], acc[nt][3]);
    }
#pragma unroll
    for (int off = 1; off <= 2; off <<= 1) {
#pragma unroll
        for (int i = 0; i < 2; i++)
#pragma unroll
            for (int h = 0; h < HEADS_T; h++) {
                accs[i][h] += __shfl_xor_sync(0xffffffffu, accs[i][h], off);
                accd[i][h] += __shfl_xor_sync(0xffffffffu, accd[i][h], off);
            }
    }
    if (tid4 == 0) {
#pragma unroll
        for (int h = 0; h < HEADS_T; h++) {
            as_out[(size_t)gr1 * HEADS_T + h] = accs[0][h];
            ad_out[(size_t)gr1 * HEADS_T + h] = accd[0][h];
            as_out[(size_t)gr2 * HEADS_T + h] = accs[1][h];
            ad_out[(size_t)gr2 * HEADS_T + h] = accd[1][h];
        }
    }
}

// ---------------- layer-1 aggregation: warp per dst node ----------------
__global__ void k_agg1(const float* __restrict__ h, const float* __restrict__ b,
                       float* __restrict__ out) {
    int n = (blockIdx.x * blockDim.x + threadIdx.x) >> 5;
    int lane = threadIdx.x & 31;
    if (n >= NN) return;
    int beg = g_off[n], end = g_off[n + 1];
    float4 ad = *(const float4*)&g_ad1[n * 4];

    float m0 = -1e30f, m1 = -1e30f, m2 = -1e30f, m3 = -1e30f;
    for (int e = beg + lane; e < end; e += 32) {
        int s = g_csr[e];
        float4 as = *(const float4*)&g_as1[s * 4];
        m0 = fmaxf(m0, lrelu(as.x + ad.x));
        m1 = fmaxf(m1, lrelu(as.y + ad.y));
        m2 = fmaxf(m2, lrelu(as.z + ad.z));
        m3 = fmaxf(m3, lrelu(as.w + ad.w));
    }
#pragma unroll
    for (int off = 16; off > 0; off >>= 1) {
        m0 = fmaxf(m0, __shfl_xor_sync(0xffffffffu, m0, off));
        m1 = fmaxf(m1, __shfl_xor_sync(0xffffffffu, m1, off));
        m2 = fmaxf(m2, __shfl_xor_sync(0xffffffffu, m2, off));
        m3 = fmaxf(m3, __shfl_xor_sync(0xffffffffu, m3, off));
    }

    float s0 = 0.f, s1 = 0.f, s2 = 0.f, s3 = 0.f;
    for (int e = beg + lane; e < end; e += 32) {
        int s = g_csr[e];
        float4 as = *(const float4*)&g_as1[s * 4];
        s0 += __expf(lrelu(as.x + ad.x) - m0);
        s1 += __expf(lrelu(as.y + ad.y) - m1);
        s2 += __expf(lrelu(as.z + ad.z) - m2);
        s3 += __expf(lrelu(as.w + ad.w) - m3);
    }
#pragma unroll
    for (int off = 16; off > 0; off >>= 1) {
        s0 += __shfl_xor_sync(0xffffffffu, s0, off);
        s1 += __shfl_xor_sync(0xffffffffu, s1, off);
        s2 += __shfl_xor_sync(0xffffffffu, s2, off);
        s3 += __shfl_xor_sync(0xffffffffu, s3, off);
    }
    float r0 = 1.f / (s0 + EPSV);
    float r1 = 1.f / (s1 + EPSV);
    float r2 = 1.f / (s2 + EPSV);
    float r3 = 1.f / (s3 + EPSV);

    float a0 = 0.f, a1 = 0.f, a2 = 0.f, a3 = 0.f;
    for (int e = beg; e < end; e++) {
        int s = g_csr[e];
        float4 as = *(const float4*)&g_as1[s * 4];
        float w0 = __expf(lrelu(as.x + ad.x) - m0) * r0;
        float w1 = __expf(lrelu(as.y + ad.y) - m1) * r1;
        float w2 = __expf(lrelu(as.z + ad.z) - m2) * r2;
        float w3 = __expf(lrelu(as.w + ad.w) - m3) * r3;
        const float* hp = h + (size_t)s * 128;
        a0 += w0 * hp[lane];
        a1 += w1 * hp[32 + lane];
        a2 += w2 * hp[64 + lane];
        a3 += w3 * hp[96 + lane];
    }
    out[(size_t)n * 128 + lane]      = sigm(a0 + b[lane]);
    out[(size_t)n * 128 + 32 + lane] = sigm(a1 + b[32 + lane]);
    out[(size_t)n * 128 + 64 + lane] = sigm(a2 + b[64 + lane]);
    out[(size_t)n * 128 + 96 + lane] = sigm(a3 + b[96 + lane]);
}

// ---------------- layer-2 aggregation (heads=1, C=64) ----------------
__global__ void k_agg2(const float* __restrict__ h, const float* __restrict__ b,
                       float* __restrict__ out) {
    int n = (blockIdx.x * blockDim.x + threadIdx.x) >> 5;
    int lane = threadIdx.x & 31;
    if (n >= NN) return;
    int beg = g_off[n], end = g_off[n + 1];
    float ad = g_ad2[n];

    float m = -1e30f;
    for (int e = beg + lane; e < end; e += 32)
        m = fmaxf(m, lrelu(g_as2[g_csr[e]] + ad));
#pragma unroll
    for (int off = 16; off > 0; off >>= 1)
        m = fmaxf(m, __shfl_xor_sync(0xffffffffu, m, off));

    float ssum = 0.f;
    for (int e = beg + lane; e < end; e += 32)
        ssum += __expf(lrelu(g_as2[g_csr[e]] + ad) - m);
#pragma unroll
    for (int off = 16; off > 0; off >>= 1)
        ssum += __shfl_xor_sync(0xffffffffu, ssum, off);
    float r = 1.f / (ssum + EPSV);

    float a0 = 0.f, a1 = 0.f;
    for (int e = beg; e < end; e++) {
        int s = g_csr[e];
        float w = __expf(lrelu(g_as2[s] + ad) - m) * r;
        const float* hp = h + (size_t)s * 64;
        a0 += w * hp[lane];
        a1 += w * hp[32 + lane];
    }
    out[(size_t)n * 64 + lane]      = sigm(a0 + b[lane]);
    out[(size_t)n * 64 + 32 + lane] = sigm(a1 + b[32 + lane]);
}

// ---------------- launch ----------------
extern "C" void kernel_launch(void* const* d_in, const int* in_sizes, int n_in,
                              void* d_out, int out_size) {
    const float* x     = (const float*)d_in[0];
    const void*  ei    = d_in[1];
    const float* W1    = (const float*)d_in[2];
    const float* at_s1 = (const float*)d_in[3];
    const float* at_d1 = (const float*)d_in[4];
    const float* b1    = (const float*)d_in[5];
    const float* W2    = (const float*)d_in[6];
    const float* at_s2 = (const float*)d_in[7];
    const float* at_d2 = (const float*)d_in[8];
    const float* b2    = (const float*)d_in[9];
    float* out = (float*)d_out;

    float *h1p, *out1p, *h2p, *as1p, *ad1p, *as2p, *ad2p;
    cudaGetSymbolAddress((void**)&h1p, g_h1);
    cudaGetSymbolAddress((void**)&out1p, g_out1);
    cudaGetSymbolAddress((void**)&h2p, g_h2);
    cudaGetSymbolAddress((void**)&as1p, g_as1);
    cudaGetSymbolAddress((void**)&ad1p, g_ad1);
    cudaGetSymbolAddress((void**)&as2p, g_as2);
    cudaGetSymbolAddress((void**)&ad2p, g_ad2);

    const int SM1 = (2 * 128 + 2 * 128) * 136 * 2 + 2 * 128 * 4;  // 140288
    const int SM2 = (2 * 128 + 2 * 64) * 136 * 2 + 2 * 64 * 4;    // 104960
    cudaFuncSetAttribute(k_mma<128, 4, 32>, cudaFuncAttributeMaxDynamicSharedMemorySize, SM1);
    cudaFuncSetAttribute(k_mma<64, 1, 64>, cudaFuncAttributeMaxDynamicSharedMemorySize, SM2);

    k_zero_detect<<<256, 256>>>((const unsigned int*)ei);
    k_convert<<<EE / 256, 256>>>(ei);
    k_scan<<<1, 1024>>>();
    k_csr<<<EE / 256, 256>>>();

    // layer 1: fused HMMA GEMM + att dots, then aggregation
    k_mma<128, 4, 32><<<NN / 128, 256, SM1>>>(x, W1, at_s1, at_d1, h1p, as1p, ad1p);
    k_agg1<<<NN / 8, 256>>>(h1p, b1, out1p);

    // layer 2
    k_mma<64, 1, 64><<<NN / 128, 256, SM2>>>(out1p, W2, at_s2, at_d2, h2p, as2p, ad2p);
    k_agg2<<<NN / 8, 256>>>(h2p, b2, out);
}

// round 5
// speedup vs baseline: 1.1775x; 1.0949x over previous
#include <cuda_runtime.h>
#include <cuda_bf16.h>
#include <stdint.h>
#include <math.h>

#define NN 65536
#define EE 1048576
#define NEG 0.2f
#define EPSV 1e-16f

// ---------------- scratch (device globals: allocation-free) ----------------
__device__ int   g_is64;
__device__ int   g_src[EE];
__device__ int   g_dst[EE];
__device__ int   g_deg[NN];
__device__ int   g_off[NN + 1];
__device__ int   g_cur[NN];
__device__ int   g_csr[EE];
__device__ float g_h1[NN * 128];
__device__ float g_as1[NN * 4];
__device__ float g_ad1[NN * 4];
__device__ float g_out1[NN * 128];
__device__ float g_h2[NN * 64];
__device__ float g_as2[NN];
__device__ float g_ad2[NN];

__device__ __forceinline__ float lrelu(float a) { return a > 0.f ? a : NEG * a; }
__device__ __forceinline__ float sigm(float x) { return 1.f / (1.f + __expf(-x)); }
__device__ __forceinline__ uint32_t pack_bf2(__nv_bfloat16 a, __nv_bfloat16 b) {
    return ((uint32_t)__bfloat16_as_ushort(b) << 16) | (uint32_t)__bfloat16_as_ushort(a);
}

__device__ __forceinline__ void mma16816(float* c, const uint32_t* a, const uint32_t* b) {
    asm volatile(
        "mma.sync.aligned.m16n8k16.row.col.f32.bf16.bf16.f32 "
        "{%0,%1,%2,%3}, {%4,%5,%6,%7}, {%8,%9}, {%0,%1,%2,%3};"
        : "+f"(c[0]), "+f"(c[1]), "+f"(c[2]), "+f"(c[3])
        : "r"(a[0]), "r"(a[1]), "r"(a[2]), "r"(a[3]), "r"(b[0]), "r"(b[1]));
}

// ---------------- preprocessing ----------------
__global__ void k_zero_detect(const unsigned int* __restrict__ ei) {
    int i = blockIdx.x * blockDim.x + threadIdx.x;
    for (int j = i; j < NN; j += gridDim.x * blockDim.x) g_deg[j] = 0;
    if (blockIdx.x == 0 && threadIdx.x == 0) {
        int is64 = 1;
        for (int k = 0; k < 128; k++)
            if (ei[2 * k + 1] != 0u) { is64 = 0; break; }
        g_is64 = is64;
    }
}

// 4 edges per thread for MLP
__global__ void k_convert(const void* __restrict__ ei) {
    int base = blockIdx.x * 1024 + threadIdx.x;
    int is64 = g_is64;
#pragma unroll
    for (int j = 0; j < 4; j++) {
        int e = base + j * 256;
        int s, d;
        if (is64) {
            const long long* p = (const long long*)ei;
            s = (int)p[e];
            d = (int)p[EE + e];
        } else {
            const int* p = (const int*)ei;
            s = p[e];
            d = p[EE + e];
        }
        g_src[e] = s;
        g_dst[e] = d;
        atomicAdd(&g_deg[d], 1);
    }
}

__global__ void __launch_bounds__(1024) k_scan() {
    __shared__ int part[1024];
    int tid = threadIdx.x;
    const int per = NN / 1024;  // 64
    int base = tid * per;
    int s = 0;
    for (int i = 0; i < per; i++) s += g_deg[base + i];
    part[tid] = s;
    __syncthreads();
    for (int off = 1; off < 1024; off <<= 1) {
        int v = (tid >= off) ? part[tid - off] : 0;
        __syncthreads();
        part[tid] += v;
        __syncthreads();
    }
    int run = (tid == 0) ? 0 : part[tid - 1];
    for (int i = 0; i < per; i++) {
        g_off[base + i] = run;
        g_cur[base + i] = run;
        run += g_deg[base + i];
    }
    if (tid == 1023) g_off[NN] = part[1023];
}

__global__ void k_csr() {
    int base = blockIdx.x * 1024 + threadIdx.x;
#pragma unroll
    for (int j = 0; j < 4; j++) {
        int e = base + j * 256;
        int pos = atomicAdd(&g_cur[g_dst[e]], 1);
        g_csr[pos] = g_src[e];
    }
}

// ---------------- fused HMMA GEMM + attention dots ----------------
template <int NB, int HEADS_T, int HC>
__global__ void __launch_bounds__(256, 1) k_mma(
    const float* __restrict__ A, const float* __restrict__ Wsrc,
    const float* __restrict__ ats, const float* __restrict__ atd,
    float* __restrict__ Hout, float* __restrict__ as_out, float* __restrict__ ad_out) {
    constexpr int PITCH = 136;
    constexpr int NT = NB / 8;
    extern __shared__ __align__(16) char smem[];
    __nv_bfloat16* Ah = (__nv_bfloat16*)smem;
    __nv_bfloat16* Al = Ah + 128 * PITCH;
    __nv_bfloat16* Bh = Al + 128 * PITCH;
    __nv_bfloat16* Bl = Bh + NB * PITCH;
    float* s_as = (float*)(Bl + NB * PITCH);
    float* s_ad = s_as + NB;

    int t = threadIdx.x, w = t >> 5, lane = t & 31;
    int gid = lane >> 2, tid4 = lane & 3;
    int row0 = blockIdx.x * 128;

#pragma unroll
    for (int i = 0; i < 16; i++) {
        int idx = i * 256 + t;
        int r = idx >> 5, c4 = idx & 31;
        float4 v = *(const float4*)&A[(size_t)(row0 + r) * 128 + c4 * 4];
        __nv_bfloat16 hx = __float2bfloat16(v.x), hy = __float2bfloat16(v.y);
        __nv_bfloat16 hz = __float2bfloat16(v.z), hw = __float2bfloat16(v.w);
        __nv_bfloat16 lx = __float2bfloat16(v.x - __bfloat162float(hx));
        __nv_bfloat16 ly = __float2bfloat16(v.y - __bfloat162float(hy));
        __nv_bfloat16 lz = __float2bfloat16(v.z - __bfloat162float(hz));
        __nv_bfloat16 lw = __float2bfloat16(v.w - __bfloat162float(hw));
        int o = r * PITCH + c4 * 4;
        *(uint2*)&Ah[o] = make_uint2(pack_bf2(hx, hy), pack_bf2(hz, hw));
        *(uint2*)&Al[o] = make_uint2(pack_bf2(lx, ly), pack_bf2(lz, lw));
    }
    for (int idx = t; idx < 128 * (NB / 4); idx += 256) {
        int k = idx / (NB / 4), n4 = idx % (NB / 4);
        float4 wv4 = *(const float4*)&Wsrc[(size_t)k * NB + n4 * 4];
        float wv[4] = {wv4.x, wv4.y, wv4.z, wv4.w};
#pragma unroll
        for (int j = 0; j < 4; j++) {
            int n = n4 * 4 + j;
            __nv_bfloat16 h = __float2bfloat16(wv[j]);
            Bh[n * PITCH + k] = h;
            Bl[n * PITCH + k] = __float2bfloat16(wv[j] - __bfloat162float(h));
        }
    }
    for (int idx = t; idx < NB; idx += 256) {
        s_as[idx] = ats[idx];
        s_ad[idx] = atd[idx];
    }
    __syncthreads();

    int wr = w * 16;
    int r1 = wr + gid, r2 = wr + gid + 8;
    float acc[NT][4];
#pragma unroll
    for (int nt = 0; nt < NT; nt++) {
        acc[nt][0] = 0.f; acc[nt][1] = 0.f; acc[nt][2] = 0.f; acc[nt][3] = 0.f;
    }
    const __nv_bfloat16* PA[3] = {Ah, Ah, Al};
    const __nv_bfloat16* PB[3] = {Bh, Bl, Bh};
#pragma unroll
    for (int p = 0; p < 3; p++) {
        const __nv_bfloat16* pa = PA[p];
        const __nv_bfloat16* pb = PB[p];
#pragma unroll
        for (int kt = 0; kt < 8; kt++) {
            int k0 = kt * 16 + tid4 * 2;
            uint32_t a[4];
            a[0] = *(const uint32_t*)&pa[r1 * PITCH + k0];
            a[1] = *(const uint32_t*)&pa[r2 * PITCH + k0];
            a[2] = *(const uint32_t*)&pa[r1 * PITCH + k0 + 8];
            a[3] = *(const uint32_t*)&pa[r2 * PITCH + k0 + 8];
#pragma unroll
            for (int nt = 0; nt < NT; nt++) {
                uint32_t b[2];
                int nr = nt * 8 + gid;
                b[0] = *(const uint32_t*)&pb[nr * PITCH + k0];
                b[1] = *(const uint32_t*)&pb[nr * PITCH + k0 + 8];
                mma16816(acc[nt], a, b);
            }
        }
    }

    float accs[2][HEADS_T], accd[2][HEADS_T];
#pragma unroll
    for (int i = 0; i < 2; i++)
#pragma unroll
        for (int h = 0; h < HEADS_T; h++) { accs[i][h] = 0.f; accd[i][h] = 0.f; }

    int gr1 = row0 + r1, gr2 = row0 + r2;
#pragma unroll
    for (int nt = 0; nt < NT; nt++) {
        const int hidx = (nt * 8) / HC;
        int c0 = nt * 8 + tid4 * 2;
        float as0 = s_as[c0], as1 = s_as[c0 + 1];
        float ad0 = s_ad[c0], ad1 = s_ad[c0 + 1];
        accs[0][hidx] += acc[nt][0] * as0 + acc[nt][1] * as1;
        accd[0][hidx] += acc[nt][0] * ad0 + acc[nt][1] * ad1;
        accs[1][hidx] += acc[nt][2] * as0 + acc[nt][3] * as1;
        accd[1][hidx] += acc[nt][2] * ad0 + acc[nt][3] * ad1;
        *(float2*)&Hout[(size_t)gr1 * NB + c0] = make_float2(acc[nt][0], acc[nt][1]);
        *(float2*)&Hout[(size_t)gr2 * NB + c0] = make_float2(acc[nt][2], acc[nt][3]);
    }
#pragma unroll
    for (int off = 1; off <= 2; off <<= 1) {
#pragma unroll
        for (int i = 0; i < 2; i++)
#pragma unroll
            for (int h = 0; h < HEADS_T; h++) {
                accs[i][h] += __shfl_xor_sync(0xffffffffu, accs[i][h], off);
                accd[i][h] += __shfl_xor_sync(0xffffffffu, accd[i][h], off);
            }
    }
    if (tid4 == 0) {
#pragma unroll
        for (int h = 0; h < HEADS_T; h++) {
            as_out[(size_t)gr1 * HEADS_T + h] = accs[0][h];
            ad_out[(size_t)gr1 * HEADS_T + h] = accd[0][h];
            as_out[(size_t)gr2 * HEADS_T + h] = accs[1][h];
            ad_out[(size_t)gr2 * HEADS_T + h] = accd[1][h];
        }
    }
}

// ---------------- layer-1 aggregation: single unnormalized pass ----------------
// out = (sum_e w_e * h_src) / (sum_e w_e + eps); w_e = exp(lrelu(as+ad)), no max-sub.
__global__ void k_agg1(const float* __restrict__ h, const float* __restrict__ b,
                       float* __restrict__ out) {
    int n = (blockIdx.x * blockDim.x + threadIdx.x) >> 5;
    int lane = threadIdx.x & 31;
    if (n >= NN) return;
    int beg = g_off[n], end = g_off[n + 1];
    float4 ad = *(const float4*)&g_ad1[n * 4];

    float a0 = 0.f, a1 = 0.f, a2 = 0.f, a3 = 0.f;
    float d0 = 0.f, d1 = 0.f, d2 = 0.f, d3 = 0.f;

    for (int e0 = beg; e0 < end; e0 += 32) {
        int cnt = min(32, end - e0);
        int s = 0;
        float w0 = 0.f, w1 = 0.f, w2 = 0.f, w3 = 0.f;
        if (lane < cnt) {
            s = g_csr[e0 + lane];
            float4 as = *(const float4*)&g_as1[s * 4];
            w0 = __expf(lrelu(as.x + ad.x));
            w1 = __expf(lrelu(as.y + ad.y));
            w2 = __expf(lrelu(as.z + ad.z));
            w3 = __expf(lrelu(as.w + ad.w));
            d0 += w0; d1 += w1; d2 += w2; d3 += w3;
        }
        for (int j = 0; j < cnt; j++) {
            int sj = __shfl_sync(0xffffffffu, s, j);
            float u0 = __shfl_sync(0xffffffffu, w0, j);
            float u1 = __shfl_sync(0xffffffffu, w1, j);
            float u2 = __shfl_sync(0xffffffffu, w2, j);
            float u3 = __shfl_sync(0xffffffffu, w3, j);
            const float* hp = h + (size_t)sj * 128;
            a0 += u0 * hp[lane];
            a1 += u1 * hp[32 + lane];
            a2 += u2 * hp[64 + lane];
            a3 += u3 * hp[96 + lane];
        }
    }
#pragma unroll
    for (int off = 16; off > 0; off >>= 1) {
        d0 += __shfl_xor_sync(0xffffffffu, d0, off);
        d1 += __shfl_xor_sync(0xffffffffu, d1, off);
        d2 += __shfl_xor_sync(0xffffffffu, d2, off);
        d3 += __shfl_xor_sync(0xffffffffu, d3, off);
    }
    float r0 = 1.f / (d0 + EPSV), r1 = 1.f / (d1 + EPSV);
    float r2 = 1.f / (d2 + EPSV), r3 = 1.f / (d3 + EPSV);
    out[(size_t)n * 128 + lane]      = sigm(a0 * r0 + b[lane]);
    out[(size_t)n * 128 + 32 + lane] = sigm(a1 * r1 + b[32 + lane]);
    out[(size_t)n * 128 + 64 + lane] = sigm(a2 * r2 + b[64 + lane]);
    out[(size_t)n * 128 + 96 + lane] = sigm(a3 * r3 + b[96 + lane]);
}

// ---------------- layer-2 aggregation (heads=1, C=64) ----------------
__global__ void k_agg2(const float* __restrict__ h, const float* __restrict__ b,
                       float* __restrict__ out) {
    int n = (blockIdx.x * blockDim.x + threadIdx.x) >> 5;
    int lane = threadIdx.x & 31;
    if (n >= NN) return;
    int beg = g_off[n], end = g_off[n + 1];
    float ad = g_ad2[n];

    float a0 = 0.f, a1 = 0.f, d = 0.f;
    for (int e0 = beg; e0 < end; e0 += 32) {
        int cnt = min(32, end - e0);
        int s = 0;
        float w = 0.f;
        if (lane < cnt) {
            s = g_csr[e0 + lane];
            w = __expf(lrelu(g_as2[s] + ad));
            d += w;
        }
        for (int j = 0; j < cnt; j++) {
            int sj = __shfl_sync(0xffffffffu, s, j);
            float u = __shfl_sync(0xffffffffu, w, j);
            const float* hp = h + (size_t)sj * 64;
            a0 += u * hp[lane];
            a1 += u * hp[32 + lane];
        }
    }
#pragma unroll
    for (int off = 16; off > 0; off >>= 1)
        d += __shfl_xor_sync(0xffffffffu, d, off);
    float r = 1.f / (d + EPSV);
    out[(size_t)n * 64 + lane]      = sigm(a0 * r + b[lane]);
    out[(size_t)n * 64 + 32 + lane] = sigm(a1 * r + b[32 + lane]);
}

// ---------------- launch ----------------
extern "C" void kernel_launch(void* const* d_in, const int* in_sizes, int n_in,
                              void* d_out, int out_size) {
    const float* x     = (const float*)d_in[0];
    const void*  ei    = d_in[1];
    const float* W1    = (const float*)d_in[2];
    const float* at_s1 = (const float*)d_in[3];
    const float* at_d1 = (const float*)d_in[4];
    const float* b1    = (const float*)d_in[5];
    const float* W2    = (const float*)d_in[6];
    const float* at_s2 = (const float*)d_in[7];
    const float* at_d2 = (const float*)d_in[8];
    const float* b2    = (const float*)d_in[9];
    float* out = (float*)d_out;

    float *h1p, *out1p, *h2p, *as1p, *ad1p, *as2p, *ad2p;
    cudaGetSymbolAddress((void**)&h1p, g_h1);
    cudaGetSymbolAddress((void**)&out1p, g_out1);
    cudaGetSymbolAddress((void**)&h2p, g_h2);
    cudaGetSymbolAddress((void**)&as1p, g_as1);
    cudaGetSymbolAddress((void**)&ad1p, g_ad1);
    cudaGetSymbolAddress((void**)&as2p, g_as2);
    cudaGetSymbolAddress((void**)&ad2p, g_ad2);

    const int SM1 = (2 * 128 + 2 * 128) * 136 * 2 + 2 * 128 * 4;
    const int SM2 = (2 * 128 + 2 * 64) * 136 * 2 + 2 * 64 * 4;
    cudaFuncSetAttribute(k_mma<128, 4, 32>, cudaFuncAttributeMaxDynamicSharedMemorySize, SM1);
    cudaFuncSetAttribute(k_mma<64, 1, 64>, cudaFuncAttributeMaxDynamicSharedMemorySize, SM2);

    k_zero_detect<<<256, 256>>>((const unsigned int*)ei);
    k_convert<<<EE / 1024, 256>>>(ei);
    k_scan<<<1, 1024>>>();
    k_csr<<<EE / 1024, 256>>>();

    k_mma<128, 4, 32><<<NN / 128, 256, SM1>>>(x, W1, at_s1, at_d1, h1p, as1p, ad1p);
    k_agg1<<<NN / 8, 256>>>(h1p, b1, out1p);

    k_mma<64, 1, 64><<<NN / 128, 256, SM2>>>(out1p, W2, at_s2, at_d2, h2p, as2p, ad2p);
    k_agg2<<<NN / 8, 256>>>(h2p, b2, out);
}